// round 16
// baseline (speedup 1.0000x reference)
#include <cuda_runtime.h>
#include <cuda_fp16.h>
#include <cstdint>

#define N_NODES 100000
#define F_IN    128
#define F_HID   64
#define F_OUT   16
#define E_MAX   1600000
#define CAP     128          // padded in-neighbor bucket capacity (Poisson(16) tail ~0)

// Scratch (allocation-free rule: __device__ globals).
// NOTE: never pass these as kernel args from host — host sees the shadow
// symbol and ATS on GB300 makes the bogus access succeed silently.
__device__ int     g_cnt [N_NODES];             // in-degree ctrs (zeroed by gather2 tail)
__device__ int     g_bucket[(size_t)N_NODES * CAP];  // in-neighbor src lists
__device__ float   g_w1t [F_IN * F_HID];        // W1 pre-rounded to tf32
__device__ __half2 g_xwsh[N_NODES * (F_HID / 2)];    // (x@W1)*dis, fp16 (gather payload)
__device__ __half2 g_hw2sh[N_NODES * (F_OUT / 2)];   // (relu(h+b1)@W2)*dis, fp16

__device__ __forceinline__ uint32_t f2tf32u(float f) {
    uint32_t r;
    asm("cvt.rna.tf32.f32 %0, %1;" : "=r"(r) : "f"(f));
    return r;
}

__device__ __forceinline__ uint32_t smem_u32(const void* p) {
    return (uint32_t)__cvta_generic_to_shared(p);
}

__device__ __forceinline__ void cp_async16(uint32_t dst, const void* src, bool valid) {
    int sz = valid ? 16 : 0;   // src-size 0 -> zero-fill
    asm volatile("cp.async.ca.shared.global [%0], [%1], 16, %2;"
                 :: "r"(dst), "l"(src), "r"(sz) : "memory");
}

// ---------------------------------------------------------------------------
// bucket build: per-block dtype sniff, decode edge, cnt[dst]++, store src.
// Also pre-rounds W1 to tf32 (first 8192 global threads).
// Requires g_cnt == 0 on entry (initial zero-init; gather2 re-zeroes each run).
// ---------------------------------------------------------------------------
__global__ void k_build(const void* __restrict__ ei, const float* __restrict__ W1,
                        int E) {
    __shared__ int s64;
    const int t = threadIdx.x;
    const int e = blockIdx.x * blockDim.x + t;

    if (t == 0) {
        // int64 little-endian with values < 2^31 has zero odd 32-bit words
        const int* p = (const int*)ei;
        int all_zero = 1;
#pragma unroll
        for (int j = 0; j < 16; ++j)
            if (p[2 * j + 1] != 0) all_zero = 0;
        s64 = all_zero;
    }
    __syncthreads();
    const bool is64 = (s64 != 0);

    if (e < F_IN * F_HID)
        g_w1t[e] = __uint_as_float(f2tf32u(W1[e]));

    if (e >= E) return;
    int s, d;
    if (is64) {
        s = (int)((const long long*)ei)[e];
        d = (int)((const long long*)ei)[e + E];
    } else {
        s = ((const int*)ei)[e];
        d = ((const int*)ei)[e + E];
    }
    if (s < 0) s = 0; if (s >= N_NODES) s = N_NODES - 1;
    if (d < 0) d = 0; if (d >= N_NODES) d = N_NODES - 1;
    int pos = atomicAdd(&g_cnt[d], 1);
    if (pos < CAP) g_bucket[d * CAP + pos] = s;
}

// ---------------------------------------------------------------------------
// GEMM1 via tf32 mma.sync, cp.async double-buffered K pipeline,
// fused dis pre-scale (dis computed inline from g_cnt), fp16 output:
//   g_xwsh[M,64] = half( (X[M,128] @ W1[128,64]) * dis )
// B-side (W) is pre-rounded in g_w1t -> no cvt on the B fragment path.
// ---------------------------------------------------------------------------
__global__ void k_gemm1(const float* __restrict__ X, int M) {
    __shared__ float sX[2][128][20];   // [stage][row][k], pad 4
    __shared__ float sW[2][16][72];    // [stage][k][n],  pad 8

    const int t    = threadIdx.x;        // 256 threads
    const int lane = t & 31;
    const int warp = t >> 5;             // 0..7
    const int wm   = warp & 3;
    const int wn   = warp >> 2;
    const int gid  = lane >> 2;
    const int tig  = lane & 3;
    const int row0 = blockIdx.x * 128;

    const int xr0 = t >> 2;
    const int xc0 = (t & 3) * 4;
    const int xr1 = (t + 256) >> 2;
    const int wkr = t >> 4;
    const int wc  = (t & 15) * 4;

    auto issue_chunk = [&](int kt, int st) {
        const float* xs0 = X + (size_t)(row0 + xr0) * F_IN + kt * 16 + xc0;
        const float* xs1 = X + (size_t)(row0 + xr1) * F_IN + kt * 16 + xc0;
        cp_async16(smem_u32(&sX[st][xr0][xc0]), xs0, row0 + xr0 < M);
        cp_async16(smem_u32(&sX[st][xr1][xc0]), xs1, row0 + xr1 < M);
        const float* ws = g_w1t + (kt * 16 + wkr) * F_HID + wc;
        cp_async16(smem_u32(&sW[st][wkr][wc]), ws, true);
        asm volatile("cp.async.commit_group;" ::: "memory");
    };

    float c[2][4][4];
#pragma unroll
    for (int i = 0; i < 2; i++)
#pragma unroll
        for (int j = 0; j < 4; j++)
#pragma unroll
            for (int k = 0; k < 4; k++) c[i][j][k] = 0.f;

    issue_chunk(0, 0);

    int st = 0;
    for (int kt = 0; kt < 8; ++kt) {
        if (kt < 7) {
            issue_chunk(kt + 1, st ^ 1);
            asm volatile("cp.async.wait_group 1;" ::: "memory");
        } else {
            asm volatile("cp.async.wait_group 0;" ::: "memory");
        }
        __syncthreads();

#pragma unroll
        for (int kc = 0; kc < 2; ++kc) {
            uint32_t b0[4], b1[4];
#pragma unroll
            for (int j = 0; j < 4; ++j) {
                int n = wn * 32 + j * 8 + gid;
                b0[j] = __float_as_uint(sW[st][kc * 8 + tig    ][n]);   // pre-rounded
                b1[j] = __float_as_uint(sW[st][kc * 8 + tig + 4][n]);
            }
            uint32_t a[2][4];
#pragma unroll
            for (int i = 0; i < 2; ++i) {
                int r = wm * 32 + i * 16;
                int k = kc * 8;
                a[i][0] = f2tf32u(sX[st][r + gid    ][k + tig    ]);
                a[i][1] = f2tf32u(sX[st][r + gid + 8][k + tig    ]);
                a[i][2] = f2tf32u(sX[st][r + gid    ][k + tig + 4]);
                a[i][3] = f2tf32u(sX[st][r + gid + 8][k + tig + 4]);
            }
#pragma unroll
            for (int i = 0; i < 2; ++i)
#pragma unroll
                for (int j = 0; j < 4; ++j) {
                    asm volatile(
                        "mma.sync.aligned.m16n8k8.row.col.f32.tf32.tf32.f32 "
                        "{%0,%1,%2,%3}, {%4,%5,%6,%7}, {%8,%9}, {%0,%1,%2,%3};"
                        : "+f"(c[i][j][0]), "+f"(c[i][j][1]),
                          "+f"(c[i][j][2]), "+f"(c[i][j][3])
                        : "r"(a[i][0]), "r"(a[i][1]), "r"(a[i][2]), "r"(a[i][3]),
                          "r"(b0[j]), "r"(b1[j]));
                }
        }
        __syncthreads();
        st ^= 1;
    }

#pragma unroll
    for (int i = 0; i < 2; ++i) {
        int gr0 = row0 + wm * 32 + i * 16 + gid;
        int gr1 = gr0 + 8;
        float ds0 = (gr0 < M) ? rsqrtf(1.0f + (float)g_cnt[gr0]) : 0.f;
        float ds1 = (gr1 < M) ? rsqrtf(1.0f + (float)g_cnt[gr1]) : 0.f;
#pragma unroll
        for (int j = 0; j < 4; ++j) {
            int col = wn * 32 + j * 8 + 2 * tig;
            if (gr0 < M)
                g_xwsh[gr0 * (F_HID / 2) + col / 2] =
                    __floats2half2_rn(c[i][j][0] * ds0, c[i][j][1] * ds0);
            if (gr1 < M)
                g_xwsh[gr1 * (F_HID / 2) + col / 2] =
                    __floats2half2_rn(c[i][j][2] * ds1, c[i][j][3] * ds1);
        }
    }
}

// ---------------------------------------------------------------------------
// FUSED gather1 + relu/bias + GEMM2 + dis pre-scale — 2 nodes per warp.
// (unchanged from R15 winner)
// ---------------------------------------------------------------------------
__global__ void k_gather1g2(const float* __restrict__ W2,
                            const float* __restrict__ b1, int N) {
    __shared__ float sW2[F_HID][17];     // W2 staged; 16+1 pad
    __shared__ float sH[16][68];         // post-relu h (64) + dis (col 64)

    const int t    = threadIdx.x;        // 256
    const int lane = t & 31;
    const int warp = t >> 5;             // 0..7
    const int node0 = blockIdx.x * 16;

    for (int i = t; i < F_HID * F_OUT; i += 256)
        sW2[i >> 4][i & 15] = W2[i];

    // phase 1: two nodes per warp, interleaved chains
    {
        int nA = node0 + warp * 2;
        int nB = nA + 1;
        bool vA = nA < N, vB = nB < N;
        int cntA = vA ? g_cnt[nA] : 0;
        int cntB = vB ? g_cnt[nB] : 0;
        int degA = min(cntA, CAP);
        int degB = min(cntB, CAP);
        const int* bkA = g_bucket + nA * CAP;
        const int* bkB = g_bucket + nB * CAP;

        float2 accA = vA ? __half22float2(g_xwsh[nA * 32 + lane])
                         : make_float2(0.f, 0.f);
        float2 accB = vB ? __half22float2(g_xwsh[nB * 32 + lane])
                         : make_float2(0.f, 0.f);

        int degM = max(degA, degB);
        for (int i = 0; i < degM; ++i) {
            if (i < degA) {
                float2 v = __half22float2(g_xwsh[bkA[i] * 32 + lane]);
                accA.x += v.x; accA.y += v.y;
            }
            if (i < degB) {
                float2 v = __half22float2(g_xwsh[bkB[i] * 32 + lane]);
                accB.x += v.x; accB.y += v.y;
            }
        }

        float2 bb = *(const float2*)(b1 + 2 * lane);
        if (vA) {
            float dd = rsqrtf(1.0f + (float)cntA);
            sH[warp * 2][2 * lane    ] = fmaxf(dd * accA.x + bb.x, 0.f);
            sH[warp * 2][2 * lane + 1] = fmaxf(dd * accA.y + bb.y, 0.f);
            if (lane == 0) sH[warp * 2][64] = dd;
        }
        if (vB) {
            float dd = rsqrtf(1.0f + (float)cntB);
            sH[warp * 2 + 1][2 * lane    ] = fmaxf(dd * accB.x + bb.x, 0.f);
            sH[warp * 2 + 1][2 * lane + 1] = fmaxf(dd * accB.y + bb.y, 0.f);
            if (lane == 0) sH[warp * 2 + 1][64] = dd;
        }
    }
    __syncthreads();

    // phase 2: thread (node_l, f) computes one output
    {
        int node_l = t >> 4;
        int f = t & 15;
        int gn = node0 + node_l;
        if (gn < N) {
            float acc = 0.f;
#pragma unroll
            for (int k = 0; k < F_HID; ++k)
                acc += sH[node_l][k] * sW2[k][f];
            float v = acc * sH[node_l][64];
            ((__half*)g_hw2sh)[gn * F_OUT + f] = __float2half(v);
        }
    }
}

// ---------------------------------------------------------------------------
// gather layer 2: 2 lanes per dst node; each lane owns 8 feats via one
// LDG.128 (int4 = 4 half2) per neighbor row half. Bucket entry for the next
// iteration is prefetched to break the bucket->row dependency chain.
//   out[d] = dis[d] * ( hw2s[d] + sum_s hw2s[s] ) + b2
// Tail: lane 0 of each node re-zeroes g_cnt[node] for the next replay.
// ---------------------------------------------------------------------------
__global__ void k_gather2(const float* __restrict__ b2, float* __restrict__ out,
                          int N) {
    int tid = blockIdx.x * blockDim.x + threadIdx.x;
    int node = tid >> 1;
    if (node >= N) return;
    int q = tid & 1;                       // row half: feats 8q .. 8q+7
    int cnt = g_cnt[node];
    int deg = min(cnt, CAP);
    const int* bk = g_bucket + node * CAP;
    const int4* rows = (const int4*)g_hw2sh;    // one row = 2 int4

    float acc[8];
    {
        int4 v = rows[node * 2 + q];           // self term
        const __half2* h = (const __half2*)&v;
#pragma unroll
        for (int j = 0; j < 4; ++j) {
            float2 f = __half22float2(h[j]);
            acc[2 * j]     = f.x;
            acc[2 * j + 1] = f.y;
        }
    }

    int s_next = (deg > 0) ? bk[0] : 0;
    for (int i = 0; i < deg; ++i) {
        int s = s_next;
        if (i + 1 < deg) s_next = bk[i + 1];   // prefetch next bucket entry
        int4 v = rows[s * 2 + q];
        const __half2* h = (const __half2*)&v;
#pragma unroll
        for (int j = 0; j < 4; ++j) {
            float2 f = __half22float2(h[j]);
            acc[2 * j]     += f.x;
            acc[2 * j + 1] += f.y;
        }
    }

    float dd = rsqrtf(1.0f + (float)cnt);
    float4 bb0 = *(const float4*)(b2 + 8 * q);
    float4 bb1 = *(const float4*)(b2 + 8 * q + 4);
    float4 o0 = make_float4(dd * acc[0] + bb0.x, dd * acc[1] + bb0.y,
                            dd * acc[2] + bb0.z, dd * acc[3] + bb0.w);
    float4 o1 = make_float4(dd * acc[4] + bb1.x, dd * acc[5] + bb1.y,
                            dd * acc[6] + bb1.z, dd * acc[7] + bb1.w);
    float* dst = out + node * F_OUT + 8 * q;
    *(float4*)dst       = o0;
    *(float4*)(dst + 4) = o1;

    if (q == 0) g_cnt[node] = 0;   // leave counters clean for next replay
}

// ---------------------------------------------------------------------------
extern "C" void kernel_launch(void* const* d_in, const int* in_sizes, int n_in,
                              void* d_out, int out_size) {
    // Bind inputs by element count (robust to metadata ordering); positional fallback.
    const float* x  = (const float*)d_in[0];
    const void*  ei = d_in[1];
    const float* W1 = (const float*)d_in[2];
    const float* b1 = (const float*)d_in[3];
    const float* W2 = (const float*)d_in[4];
    const float* b2 = (const float*)d_in[5];
    int x_elems = in_sizes[0];
    int e_elems = in_sizes[1];
    for (int i = 0; i < n_in; ++i) {
        int sz = in_sizes[i];
        if (sz == N_NODES * F_IN)      { x  = (const float*)d_in[i]; x_elems = sz; }
        else if (sz == 2 * E_MAX)      { ei = d_in[i];               e_elems = sz; }
        else if (sz == F_IN * F_HID)   { W1 = (const float*)d_in[i]; }
        else if (sz == F_HID)          { b1 = (const float*)d_in[i]; }
        else if (sz == F_HID * F_OUT)  { W2 = (const float*)d_in[i]; }
        else if (sz == F_OUT)          { b2 = (const float*)d_in[i]; }
    }
    float* out = (float*)d_out;

    const int N = x_elems / F_IN;       // 100000
    const int E = e_elems / 2;          // 1600000

    const int T = 256;

    // build (fused sniff + W1 tf32 pre-round; cnt zeroed by prior gather2)
    k_build<<<(E + T - 1) / T, T>>>(ei, W1, E);

    // layer 1 GEMM (tf32 mma + cp.async pipeline, inline-dis fp16 epilogue)
    k_gemm1<<<(N + 127) / 128, 256>>>(x, N);

    // fused layer-1 aggregation + layer-2 GEMM
    k_gather1g2<<<(N + 15) / 16, 256>>>(W2, b1, N);

    // layer-2 aggregation + bias (+ counter re-zero), 2 lanes/node
    k_gather2<<<(N * 2 + T - 1) / T, T>>>(b2, out, N);
}

// round 17
// speedup vs baseline: 1.0218x; 1.0218x over previous
#include <cuda_runtime.h>
#include <cuda_fp16.h>
#include <cstdint>

#define N_NODES 100000
#define F_IN    128
#define F_HID   64
#define F_OUT   16
#define E_MAX   1600000
#define CAP     128          // padded in-neighbor bucket capacity (Poisson(16) tail ~0)

// Scratch (allocation-free rule: __device__ globals).
// NOTE: never pass these as kernel args from host — host sees the shadow
// symbol and ATS on GB300 makes the bogus access succeed silently.
__device__ int     g_cnt [N_NODES];             // in-degree ctrs (zeroed by gather2 tail)
__device__ int     g_bucket[(size_t)N_NODES * CAP];  // in-neighbor src lists
__device__ float   g_w1t [F_IN * F_HID];        // W1 pre-rounded to tf32 (rna)
__device__ __half2 g_xwsh[N_NODES * (F_HID / 2)];    // (x@W1)*dis, fp16 (gather payload)
__device__ __half2 g_hw2sh[N_NODES * (F_OUT / 2)];   // (relu(h+b1)@W2)*dis, fp16

__device__ __forceinline__ uint32_t f2tf32u(float f) {
    uint32_t r;
    asm("cvt.rna.tf32.f32 %0, %1;" : "=r"(r) : "f"(f));
    return r;
}

__device__ __forceinline__ uint32_t smem_u32(const void* p) {
    return (uint32_t)__cvta_generic_to_shared(p);
}

__device__ __forceinline__ void cp_async16(uint32_t dst, const void* src, bool valid) {
    int sz = valid ? 16 : 0;   // src-size 0 -> zero-fill
    asm volatile("cp.async.ca.shared.global [%0], [%1], 16, %2;"
                 :: "r"(dst), "l"(src), "r"(sz) : "memory");
}

// ---------------------------------------------------------------------------
// bucket build: per-block dtype sniff, decode edge, cnt[dst]++, store src.
// Also pre-rounds W1 to tf32 (first 8192 global threads).
// Requires g_cnt == 0 on entry (initial zero-init; gather2 re-zeroes each run).
// ---------------------------------------------------------------------------
__global__ void k_build(const void* __restrict__ ei, const float* __restrict__ W1,
                        int E) {
    __shared__ int s64;
    const int t = threadIdx.x;
    const int e = blockIdx.x * blockDim.x + t;

    if (t == 0) {
        // int64 little-endian with values < 2^31 has zero odd 32-bit words
        const int* p = (const int*)ei;
        int all_zero = 1;
#pragma unroll
        for (int j = 0; j < 16; ++j)
            if (p[2 * j + 1] != 0) all_zero = 0;
        s64 = all_zero;
    }
    __syncthreads();
    const bool is64 = (s64 != 0);

    if (e < F_IN * F_HID)
        g_w1t[e] = __uint_as_float(f2tf32u(W1[e]));

    if (e >= E) return;
    int s, d;
    if (is64) {
        s = (int)((const long long*)ei)[e];
        d = (int)((const long long*)ei)[e + E];
    } else {
        s = ((const int*)ei)[e];
        d = ((const int*)ei)[e + E];
    }
    if (s < 0) s = 0; if (s >= N_NODES) s = N_NODES - 1;
    if (d < 0) d = 0; if (d >= N_NODES) d = N_NODES - 1;
    int pos = atomicAdd(&g_cnt[d], 1);
    if (pos < CAP) g_bucket[d * CAP + pos] = s;
}

// ---------------------------------------------------------------------------
// GEMM1 via tf32 mma.sync, cp.async double-buffered K pipeline,
// fused dis pre-scale (dis computed inline from g_cnt), fp16 output:
//   g_xwsh[M,64] = half( (X[M,128] @ W1[128,64]) * dis )
// B-side pre-rounded (rna) in g_w1t; A-side passes raw fp32 bits — the
// tf32 MMA hardware reads only the tf32 bit positions (truncation), whose
// per-element error contributes a random walk (not a coherent bias) to the
// K=128 dot products. Saves ~128 cvt issue slots per thread.
// ---------------------------------------------------------------------------
__global__ void k_gemm1(const float* __restrict__ X, int M) {
    __shared__ float sX[2][128][20];   // [stage][row][k], pad 4
    __shared__ float sW[2][16][72];    // [stage][k][n],  pad 8

    const int t    = threadIdx.x;        // 256 threads
    const int lane = t & 31;
    const int warp = t >> 5;             // 0..7
    const int wm   = warp & 3;
    const int wn   = warp >> 2;
    const int gid  = lane >> 2;
    const int tig  = lane & 3;
    const int row0 = blockIdx.x * 128;

    const int xr0 = t >> 2;
    const int xc0 = (t & 3) * 4;
    const int xr1 = (t + 256) >> 2;
    const int wkr = t >> 4;
    const int wc  = (t & 15) * 4;

    auto issue_chunk = [&](int kt, int st) {
        const float* xs0 = X + (size_t)(row0 + xr0) * F_IN + kt * 16 + xc0;
        const float* xs1 = X + (size_t)(row0 + xr1) * F_IN + kt * 16 + xc0;
        cp_async16(smem_u32(&sX[st][xr0][xc0]), xs0, row0 + xr0 < M);
        cp_async16(smem_u32(&sX[st][xr1][xc0]), xs1, row0 + xr1 < M);
        const float* ws = g_w1t + (kt * 16 + wkr) * F_HID + wc;
        cp_async16(smem_u32(&sW[st][wkr][wc]), ws, true);
        asm volatile("cp.async.commit_group;" ::: "memory");
    };

    float c[2][4][4];
#pragma unroll
    for (int i = 0; i < 2; i++)
#pragma unroll
        for (int j = 0; j < 4; j++)
#pragma unroll
            for (int k = 0; k < 4; k++) c[i][j][k] = 0.f;

    issue_chunk(0, 0);

    int st = 0;
    for (int kt = 0; kt < 8; ++kt) {
        if (kt < 7) {
            issue_chunk(kt + 1, st ^ 1);
            asm volatile("cp.async.wait_group 1;" ::: "memory");
        } else {
            asm volatile("cp.async.wait_group 0;" ::: "memory");
        }
        __syncthreads();

#pragma unroll
        for (int kc = 0; kc < 2; ++kc) {
            uint32_t b0[4], b1[4];
#pragma unroll
            for (int j = 0; j < 4; ++j) {
                int n = wn * 32 + j * 8 + gid;
                b0[j] = __float_as_uint(sW[st][kc * 8 + tig    ][n]);   // pre-rounded
                b1[j] = __float_as_uint(sW[st][kc * 8 + tig + 4][n]);
            }
            uint32_t a[2][4];
#pragma unroll
            for (int i = 0; i < 2; ++i) {
                int r = wm * 32 + i * 16;
                int k = kc * 8;
                a[i][0] = __float_as_uint(sX[st][r + gid    ][k + tig    ]);
                a[i][1] = __float_as_uint(sX[st][r + gid + 8][k + tig    ]);
                a[i][2] = __float_as_uint(sX[st][r + gid    ][k + tig + 4]);
                a[i][3] = __float_as_uint(sX[st][r + gid + 8][k + tig + 4]);
            }
#pragma unroll
            for (int i = 0; i < 2; ++i)
#pragma unroll
                for (int j = 0; j < 4; ++j) {
                    asm volatile(
                        "mma.sync.aligned.m16n8k8.row.col.f32.tf32.tf32.f32 "
                        "{%0,%1,%2,%3}, {%4,%5,%6,%7}, {%8,%9}, {%0,%1,%2,%3};"
                        : "+f"(c[i][j][0]), "+f"(c[i][j][1]),
                          "+f"(c[i][j][2]), "+f"(c[i][j][3])
                        : "r"(a[i][0]), "r"(a[i][1]), "r"(a[i][2]), "r"(a[i][3]),
                          "r"(b0[j]), "r"(b1[j]));
                }
        }
        __syncthreads();
        st ^= 1;
    }

#pragma unroll
    for (int i = 0; i < 2; ++i) {
        int gr0 = row0 + wm * 32 + i * 16 + gid;
        int gr1 = gr0 + 8;
        float ds0 = (gr0 < M) ? rsqrtf(1.0f + (float)g_cnt[gr0]) : 0.f;
        float ds1 = (gr1 < M) ? rsqrtf(1.0f + (float)g_cnt[gr1]) : 0.f;
#pragma unroll
        for (int j = 0; j < 4; ++j) {
            int col = wn * 32 + j * 8 + 2 * tig;
            if (gr0 < M)
                g_xwsh[gr0 * (F_HID / 2) + col / 2] =
                    __floats2half2_rn(c[i][j][0] * ds0, c[i][j][1] * ds0);
            if (gr1 < M)
                g_xwsh[gr1 * (F_HID / 2) + col / 2] =
                    __floats2half2_rn(c[i][j][2] * ds1, c[i][j][3] * ds1);
        }
    }
}

// ---------------------------------------------------------------------------
// FUSED gather1 + relu/bias + GEMM2 + dis pre-scale — 2 nodes per warp.
// (unchanged from R15 winner)
// ---------------------------------------------------------------------------
__global__ void k_gather1g2(const float* __restrict__ W2,
                            const float* __restrict__ b1, int N) {
    __shared__ float sW2[F_HID][17];     // W2 staged; 16+1 pad
    __shared__ float sH[16][68];         // post-relu h (64) + dis (col 64)

    const int t    = threadIdx.x;        // 256
    const int lane = t & 31;
    const int warp = t >> 5;             // 0..7
    const int node0 = blockIdx.x * 16;

    for (int i = t; i < F_HID * F_OUT; i += 256)
        sW2[i >> 4][i & 15] = W2[i];

    // phase 1: two nodes per warp, interleaved chains
    {
        int nA = node0 + warp * 2;
        int nB = nA + 1;
        bool vA = nA < N, vB = nB < N;
        int cntA = vA ? g_cnt[nA] : 0;
        int cntB = vB ? g_cnt[nB] : 0;
        int degA = min(cntA, CAP);
        int degB = min(cntB, CAP);
        const int* bkA = g_bucket + nA * CAP;
        const int* bkB = g_bucket + nB * CAP;

        float2 accA = vA ? __half22float2(g_xwsh[nA * 32 + lane])
                         : make_float2(0.f, 0.f);
        float2 accB = vB ? __half22float2(g_xwsh[nB * 32 + lane])
                         : make_float2(0.f, 0.f);

        int degM = max(degA, degB);
        for (int i = 0; i < degM; ++i) {
            if (i < degA) {
                float2 v = __half22float2(g_xwsh[bkA[i] * 32 + lane]);
                accA.x += v.x; accA.y += v.y;
            }
            if (i < degB) {
                float2 v = __half22float2(g_xwsh[bkB[i] * 32 + lane]);
                accB.x += v.x; accB.y += v.y;
            }
        }

        float2 bb = *(const float2*)(b1 + 2 * lane);
        if (vA) {
            float dd = rsqrtf(1.0f + (float)cntA);
            sH[warp * 2][2 * lane    ] = fmaxf(dd * accA.x + bb.x, 0.f);
            sH[warp * 2][2 * lane + 1] = fmaxf(dd * accA.y + bb.y, 0.f);
            if (lane == 0) sH[warp * 2][64] = dd;
        }
        if (vB) {
            float dd = rsqrtf(1.0f + (float)cntB);
            sH[warp * 2 + 1][2 * lane    ] = fmaxf(dd * accB.x + bb.x, 0.f);
            sH[warp * 2 + 1][2 * lane + 1] = fmaxf(dd * accB.y + bb.y, 0.f);
            if (lane == 0) sH[warp * 2 + 1][64] = dd;
        }
    }
    __syncthreads();

    // phase 2: thread (node_l, f) computes one output
    {
        int node_l = t >> 4;
        int f = t & 15;
        int gn = node0 + node_l;
        if (gn < N) {
            float acc = 0.f;
#pragma unroll
            for (int k = 0; k < F_HID; ++k)
                acc += sH[node_l][k] * sW2[k][f];
            float v = acc * sH[node_l][64];
            ((__half*)g_hw2sh)[gn * F_OUT + f] = __float2half(v);
        }
    }
}

// ---------------------------------------------------------------------------
// gather layer 2 (R15 winner shape): 8 lanes per dst node, one half2 per
// lane, fp32 accumulate, float2 stores, 32-bit indexing.
//   out[d] = dis[d] * ( hw2s[d] + sum_s hw2s[s] ) + b2
// Tail: lane 0 of each node re-zeroes g_cnt[node] for the next replay.
// ---------------------------------------------------------------------------
__global__ void k_gather2(const float* __restrict__ b2, float* __restrict__ out,
                          int N) {
    int tid = blockIdx.x * blockDim.x + threadIdx.x;
    int node = tid >> 3;
    if (node >= N) return;
    int q = tid & 7;                       // half2 index: feats 2q, 2q+1
    int cnt = g_cnt[node];
    int deg = min(cnt, CAP);
    const int* bk = g_bucket + node * CAP;

    float2 acc = __half22float2(g_hw2sh[node * 8 + q]);   // self term
    for (int i = 0; i < deg; ++i) {
        float2 v = __half22float2(g_hw2sh[bk[i] * 8 + q]);
        acc.x += v.x; acc.y += v.y;
    }
    float dd = rsqrtf(1.0f + (float)cnt);
    float2 bb = *(const float2*)(b2 + 2 * q);
    float2 o = make_float2(dd * acc.x + bb.x, dd * acc.y + bb.y);
    *(float2*)(out + node * F_OUT + 2 * q) = o;

    if (q == 0) g_cnt[node] = 0;   // leave counters clean for next replay
}

// ---------------------------------------------------------------------------
extern "C" void kernel_launch(void* const* d_in, const int* in_sizes, int n_in,
                              void* d_out, int out_size) {
    // Bind inputs by element count (robust to metadata ordering); positional fallback.
    const float* x  = (const float*)d_in[0];
    const void*  ei = d_in[1];
    const float* W1 = (const float*)d_in[2];
    const float* b1 = (const float*)d_in[3];
    const float* W2 = (const float*)d_in[4];
    const float* b2 = (const float*)d_in[5];
    int x_elems = in_sizes[0];
    int e_elems = in_sizes[1];
    for (int i = 0; i < n_in; ++i) {
        int sz = in_sizes[i];
        if (sz == N_NODES * F_IN)      { x  = (const float*)d_in[i]; x_elems = sz; }
        else if (sz == 2 * E_MAX)      { ei = d_in[i];               e_elems = sz; }
        else if (sz == F_IN * F_HID)   { W1 = (const float*)d_in[i]; }
        else if (sz == F_HID)          { b1 = (const float*)d_in[i]; }
        else if (sz == F_HID * F_OUT)  { W2 = (const float*)d_in[i]; }
        else if (sz == F_OUT)          { b2 = (const float*)d_in[i]; }
    }
    float* out = (float*)d_out;

    const int N = x_elems / F_IN;       // 100000
    const int E = e_elems / 2;          // 1600000

    const int T = 256;

    // build (fused sniff + W1 tf32 pre-round; cnt zeroed by prior gather2)
    k_build<<<(E + T - 1) / T, T>>>(ei, W1, E);

    // layer 1 GEMM (tf32 mma + cp.async pipeline, inline-dis fp16 epilogue)
    k_gemm1<<<(N + 127) / 128, 256>>>(x, N);

    // fused layer-1 aggregation + layer-2 GEMM
    k_gather1g2<<<(N + 15) / 16, 256>>>(W2, b1, N);

    // layer-2 aggregation + bias (+ counter re-zero), 8 lanes/node
    k_gather2<<<(N * 8 + T - 1) / T, T>>>(b2, out, N);
}